// round 13
// baseline (speedup 1.0000x reference)
#include <cuda_runtime.h>
#include <cstddef>

// Problem constants
#define NX 64
#define NU 32
#define NY 32
#define NW 64
#define BB 256
#define TT 2048

// Yinv^T (written by inv_kernel): gYinvT[j*64+i] = Yinv[i][j]
__device__ float gYinvT[64 * 64];

// Per-thread packed weights gWT[s][96] (chunk = 4 floats = 2 u64):
//  s in [0,128):   z half: row=s>>1, h=s&1. Fused row = [Gzx(64)|Gzw(64)|Gzu(32)|D21t(32)]
//                  i0..15: c=h+2i; i16..19: c=32+h+2(i-16); i20..23: c=40+h+2(i-20)
//  s in [128,256): x half: idx=s-128, row=[Atil|B2til|B1til|pad]
//                  i0..15: c=h+2i; i16..19: c=32+h+2(i-16)
//  s in [256,320): y half: idx=s-256, row=[C1|D12|D11|pad], same 20-chunk map
__device__ float gWT[320 * 96];

// Trajectory stream: gVseq[b][t][128] = [x_t | w_t], t in [0,TT)
__device__ __align__(16) float gVseq[(size_t)BB * TT * 128];

// ---------------------------------------------------------------------------
// inv_kernel: Newton-Schulz inverse of Y (X0 = 2I - Y, 3 iters), all in smem.
// ---------------------------------------------------------------------------
__global__ void __launch_bounds__(256, 1)
inv_kernel(const float* __restrict__ Y)
{
    __shared__ float sY[4096];
    __shared__ float sX[4096];
    __shared__ float sQ[4096];
    const int tid = threadIdx.x;      // 256
    const int row = tid >> 2;         // 0..63
    const int g16 = tid & 3;          // 16-col group

    for (int e = tid; e < 4096; e += 256) sY[e] = Y[e];
    __syncthreads();
    for (int e = tid; e < 4096; e += 256) {
        int i = e >> 6, j = e & 63;
        sX[e] = ((i == j) ? 2.0f : 0.0f) - sY[e];
    }
    __syncthreads();

    for (int it = 0; it < 3; it++) {
        float acc[16];
        #pragma unroll
        for (int m = 0; m < 16; m++) acc[m] = 0.0f;
        for (int k = 0; k < 64; k++) {
            float a = sY[row * 64 + k];
            const float4* xr = (const float4*)(sX + k * 64 + g16 * 16);
            float4 x0 = xr[0], x1 = xr[1], x2 = xr[2], x3 = xr[3];
            acc[0]+=a*x0.x; acc[1]+=a*x0.y; acc[2]+=a*x0.z; acc[3]+=a*x0.w;
            acc[4]+=a*x1.x; acc[5]+=a*x1.y; acc[6]+=a*x1.z; acc[7]+=a*x1.w;
            acc[8]+=a*x2.x; acc[9]+=a*x2.y; acc[10]+=a*x2.z; acc[11]+=a*x2.w;
            acc[12]+=a*x3.x; acc[13]+=a*x3.y; acc[14]+=a*x3.z; acc[15]+=a*x3.w;
        }
        #pragma unroll
        for (int m = 0; m < 16; m++) {
            int j = g16 * 16 + m;
            sQ[row * 64 + j] = ((j == row) ? 2.0f : 0.0f) - acc[m];
        }
        __syncthreads();
        #pragma unroll
        for (int m = 0; m < 16; m++) acc[m] = 0.0f;
        for (int k = 0; k < 64; k++) {
            float a = sX[row * 64 + k];
            const float4* qr = (const float4*)(sQ + k * 64 + g16 * 16);
            float4 q0 = qr[0], q1 = qr[1], q2 = qr[2], q3 = qr[3];
            acc[0]+=a*q0.x; acc[1]+=a*q0.y; acc[2]+=a*q0.z; acc[3]+=a*q0.w;
            acc[4]+=a*q1.x; acc[5]+=a*q1.y; acc[6]+=a*q1.z; acc[7]+=a*q1.w;
            acc[8]+=a*q2.x; acc[9]+=a*q2.y; acc[10]+=a*q2.z; acc[11]+=a*q2.w;
            acc[12]+=a*q3.x; acc[13]+=a*q3.y; acc[14]+=a*q3.z; acc[15]+=a*q3.w;
        }
        __syncthreads();   // all reads of sX done before overwrite
        #pragma unroll
        for (int m = 0; m < 16; m++) sX[row * 64 + g16 * 16 + m] = acc[m];
        __syncthreads();
    }
    // write transpose
    for (int e = tid; e < 4096; e += 256) {
        int i = e >> 6, j = e & 63;
        gYinvT[j * 64 + i] = sX[e];
    }
}

// ---------------------------------------------------------------------------
// fold_kernel: grid 160 — CTA r builds fused row r and writes gWT directly.
// ---------------------------------------------------------------------------
__global__ void __launch_bounds__(128, 1)
fold_kernel(const float* __restrict__ lambdas,
            const float* __restrict__ A,
            const float* __restrict__ B1,
            const float* __restrict__ B2,
            const float* __restrict__ C1,
            const float* __restrict__ D11,
            const float* __restrict__ D12,
            const float* __restrict__ C2,
            const float* __restrict__ D21)
{
    __shared__ float svv[64];
    __shared__ float sH[64];
    __shared__ float rowbuf[192];
    const int r = blockIdx.x;    // 0..159
    const int t = threadIdx.x;   // 0..127

    if (r < 64) {
        // z row: [Gzx | Gzw | Gzu | D21t], Gz* = H @ [A,B2,B1], H = C2t @ YinvT
        float linv = 1.0f / lambdas[r];
        if (t < 64) svv[t] = C2[r * 64 + t] * linv;
        __syncthreads();
        if (t < 64) {
            float acc = 0.0f;
            #pragma unroll 8
            for (int j = 0; j < 64; j++) acc += svv[j] * gYinvT[j * 64 + t];
            sH[t] = acc;
        }
        __syncthreads();
        if (t < 64) {
            float ax = 0.0f, aw = 0.0f;
            #pragma unroll 8
            for (int i = 0; i < 64; i++) {
                float hh = sH[i];
                ax += hh * A[i * 64 + t];
                aw += hh * B2[i * 64 + t];
            }
            rowbuf[t] = ax;
            rowbuf[64 + t] = aw;
        } else if (t < 96) {
            int m = t - 64;
            float au = 0.0f;
            #pragma unroll 8
            for (int i = 0; i < 64; i++) au += sH[i] * B1[i * 32 + m];
            rowbuf[128 + m] = au;
        } else {
            int m = t - 96;
            rowbuf[160 + m] = D21[r * 32 + m] * linv;
        }
        __syncthreads();
        // pack: 2 slots (2r, 2r+1), 96 entries each, 24 chunks
        for (int e = t; e < 192; e += 128) {
            int h = (e >= 96) ? 1 : 0;
            int ee = e - 96 * h;
            int i = ee >> 2, jj = ee & 3;
            int c;
            if (i < 16)      c = h + 2 * i;
            else if (i < 20) c = 32 + h + 2 * (i - 16);
            else             c = 40 + h + 2 * (i - 20);
            gWT[(2 * r + h) * 96 + ee] = rowbuf[4 * c + jj];
        }
    } else if (r < 128) {
        // x row: [Atil | B2til | B1til], *til = YinvT-row @ [A,B2,B1]
        int j = r - 64;
        if (t < 64) svv[t] = gYinvT[j * 64 + t];
        __syncthreads();
        if (t < 64) {
            float aa = 0.0f, ab = 0.0f;
            #pragma unroll 8
            for (int i = 0; i < 64; i++) {
                float yi = svv[i];
                aa += yi * A[i * 64 + t];
                ab += yi * B2[i * 64 + t];
            }
            rowbuf[t] = aa;
            rowbuf[64 + t] = ab;
        } else if (t < 96) {
            int m = t - 64;
            float au = 0.0f;
            #pragma unroll 8
            for (int i = 0; i < 64; i++) au += svv[i] * B1[i * 32 + m];
            rowbuf[128 + m] = au;
        }
        __syncthreads();
        for (int e = t; e < 160; e += 128) {
            int h = (e >= 80) ? 1 : 0;
            int ee = e - 80 * h;
            int i = ee >> 2, jj = ee & 3;
            int c = (i < 16) ? (h + 2 * i) : (32 + h + 2 * (i - 16));
            gWT[(128 + 2 * j + h) * 96 + ee] = rowbuf[4 * c + jj];
        }
    } else {
        // y row: [C1 | D12 | D11]
        int j = r - 128;
        if (t < 64) {
            rowbuf[t]      = C1[j * 64 + t];
            rowbuf[64 + t] = D12[j * 64 + t];
        } else if (t < 96) {
            rowbuf[128 + (t - 64)] = D11[j * 32 + (t - 64)];
        }
        __syncthreads();
        for (int e = t; e < 160; e += 128) {
            int h = (e >= 80) ? 1 : 0;
            int ee = e - 80 * h;
            int i = ee >> 2, jj = ee & 3;
            int c = (i < 16) ? (h + 2 * i) : (32 + h + 2 * (i - 16));
            gWT[(256 + 2 * j + h) * 96 + ee] = rowbuf[4 * c + jj];
        }
    }
}

// ---------------------------------------------------------------------------
// helpers
// ---------------------------------------------------------------------------
__device__ __forceinline__ float2 u64_as_f2(unsigned long long x) {
    float2 r;
    asm("mov.b64 {%0, %1}, %2;" : "=f"(r.x), "=f"(r.y) : "l"(x));
    return r;
}
#define FFMA2(acc, w, vv) \
    asm("fma.rn.f32x2 %0, %1, %2, %0;" : "+l"(acc) : "l"(w), "l"(vv))
#define ADDF2(d, a, b) \
    asm("add.rn.f32x2 %0, %1, %2;" : "=l"(d) : "l"(a), "l"(b))
#define BARB(id) asm volatile("bar.sync %0, 256;" :: "r"(id) : "memory")

__device__ __forceinline__ float fast_tanh(float x) {
    float e;
    asm("ex2.approx.f32 %0, %1;" : "=f"(e) : "f"(x * 2.8853900817779268f));
    return 1.0f - __fdividef(2.0f, e + 1.0f);
}

// Bulk flush: 16 steps [T0, T0+16) from the 32-deep ring to gVseq.
// 512 float4 per batch, 2 per thread, coalesced.
__device__ __forceinline__ void flush16(const float* ring, float4* gv4,
                                        int T0, int bt) {
    #pragma unroll
    for (int k = 0; k < 2; k++) {
        int F = bt + 256 * k;          // 0..511
        int sl = F >> 5;               // local step 0..15
        int c4 = F & 31;               // float4 column
        int step = T0 + sl;
        float4 val = *(const float4*)(ring + ((step & 31) * 128) + 4 * c4);
        gv4[(size_t)step * 32 + c4] = val;
    }
}

// ---------------------------------------------------------------------------
// Sequential kernel: 128 CTAs x 512 threads, 2 batch chains per CTA,
// ONE barrier per step (substituted recurrence:
//   w_{t+1} = tanh(Gzx x_t + Gzw w_t + Gzu u_t + D21t u_{t+1})
//   x_{t+1} = Atil x_t + B2til w_t + B1til u_t ).
// State lives in a 32-deep smem ring [slot][x(64)|w(64)]; bulk flush every 16
// steps to gVseq. u-partials software-pipelined off the critical path.
// batch=(wid>>2)&1, isZ=wid>=8 -> every SMSP: 2 z + 2 x warps.
// ---------------------------------------------------------------------------
__global__ void __launch_bounds__(512, 1)
rnn_kernel(const float* __restrict__ xpred, float* __restrict__ out, int write_xfinal)
{
    __shared__ __align__(16) float sv[2 * 4224];   // per batch: ring 32*128 | u 4*32

    const int tid  = threadIdx.x;
    const int wid  = tid >> 5;
    const int lane = tid & 31;

    const int isZ   = (wid >= 8);
    const int batch = (wid >> 2) & 1;
    const int widx  = wid & 3;
    const int idx   = widx * 32 + lane;   // 0..127
    const int row   = idx >> 1;           // 0..63
    const int h     = idx & 1;
    const int bt    = (isZ ? 128 : 0) + idx;   // per-batch thread id

    float* ring = sv + batch * 4224;      // [32][128]
    float* vu   = ring + 4096;            // [4][32]
    const int bg = blockIdx.x * 2 + batch;
    const float* uptr = xpred + (size_t)bg * TT * NU;
    float4* gv4 = (float4*)(gVseq + (size_t)bg * TT * 128);
    const int barid = batch + 1;

    if (isZ) {
        // ================= Z half: 16 crit chunks + 8 pu chunks ===========
        unsigned long long wreg[48];
        {
            const unsigned long long* grow = (const unsigned long long*)(gWT + idx * 96);
            #pragma unroll
            for (int i = 0; i < 48; i++) wreg[i] = grow[i];
        }
        BARB(barid);   // u_0..u_2 staged, x_0 zeroed (slot 0)

        // prologue: w_0 = tanh(D21t u_0)
        {
            const float* u0p = vu + 4 * h;
            unsigned long long b0 = 0ull, b1 = 0ull;
            #pragma unroll
            for (int i = 20; i < 24; i += 2) {
                ulonglong2 q0 = *(const ulonglong2*)(u0p + 8 * (i - 20));
                ulonglong2 q1 = *(const ulonglong2*)(u0p + 8 * (i - 20) + 8);
                FFMA2(b0, wreg[2*i],   q0.x); FFMA2(b1, wreg[2*i+1], q0.y);
                FFMA2(b0, wreg[2*i+2], q1.x); FFMA2(b1, wreg[2*i+3], q1.y);
            }
            ADDF2(b0, b0, b1);
            float2 pp = u64_as_f2(b0);
            float zs = pp.x + pp.y;
            zs += __shfl_xor_sync(0xffffffffu, zs, 1);
            if (h == 0) ring[64 + row] = fast_tanh(zs);   // slot 0 w-part
        }
        // pu for step 0: Gzu u_0 + D21t u_1
        unsigned long long pu;
        {
            const float* ua = vu + 4 * h;
            const float* ub = vu + 32 + 4 * h;
            unsigned long long b0 = 0ull, b1 = 0ull;
            #pragma unroll
            for (int i = 16; i < 20; i += 2) {
                ulonglong2 q0 = *(const ulonglong2*)(ua + 8 * (i - 16));
                ulonglong2 q1 = *(const ulonglong2*)(ua + 8 * (i - 16) + 8);
                FFMA2(b0, wreg[2*i],   q0.x); FFMA2(b1, wreg[2*i+1], q0.y);
                FFMA2(b0, wreg[2*i+2], q1.x); FFMA2(b1, wreg[2*i+3], q1.y);
            }
            #pragma unroll
            for (int i = 20; i < 24; i += 2) {
                ulonglong2 q0 = *(const ulonglong2*)(ub + 8 * (i - 20));
                ulonglong2 q1 = *(const ulonglong2*)(ub + 8 * (i - 20) + 8);
                FFMA2(b0, wreg[2*i],   q0.x); FFMA2(b1, wreg[2*i+1], q0.y);
                FFMA2(b0, wreg[2*i+2], q1.x); FFMA2(b1, wreg[2*i+3], q1.y);
            }
            ADDF2(pu, b0, b1);
        }
        BARB(barid);

        for (int t = 0; t < TT; t++) {
            if ((t & 15) == 0 && t != 0) flush16(ring, gv4, t - 16, bt);

            const float* vp = ring + (t & 31) * 128 + 4 * h;
            unsigned long long a0=0ull,a1=0ull,a2=0ull,a3=0ull;
            #pragma unroll
            for (int i = 0; i < 8; i += 2) {
                ulonglong2 v0 = *(const ulonglong2*)(vp + 8 * i);
                ulonglong2 v1 = *(const ulonglong2*)(vp + 8 * i + 8);
                FFMA2(a0, wreg[2*i],   v0.x); FFMA2(a1, wreg[2*i+1], v0.y);
                FFMA2(a2, wreg[2*i+2], v1.x); FFMA2(a3, wreg[2*i+3], v1.y);
            }
            #pragma unroll
            for (int i = 8; i < 16; i += 2) {
                ulonglong2 v0 = *(const ulonglong2*)(vp + 64 + 8 * (i - 8));
                ulonglong2 v1 = *(const ulonglong2*)(vp + 64 + 8 * (i - 8) + 8);
                FFMA2(a0, wreg[2*i],   v0.x); FFMA2(a1, wreg[2*i+1], v0.y);
                FFMA2(a2, wreg[2*i+2], v1.x); FFMA2(a3, wreg[2*i+3], v1.y);
            }
            ADDF2(a0, a0, a2); ADDF2(a1, a1, a3);
            ADDF2(a0, a0, a1); ADDF2(a0, a0, pu);
            float2 pp = u64_as_f2(a0);
            float zs = pp.x + pp.y;
            zs += __shfl_xor_sync(0xffffffffu, zs, 1);
            float w = fast_tanh(zs);
            if (h == 0) ring[((t + 1) & 31) * 128 + 64 + row] = w;   // w_{t+1}

            // pu for next step: Gzu u_{t+1} + D21t u_{t+2}
            {
                const float* ua = vu + ((t + 1) & 3) * 32 + 4 * h;
                const float* ub = vu + ((t + 2) & 3) * 32 + 4 * h;
                unsigned long long b0 = 0ull, b1 = 0ull;
                #pragma unroll
                for (int i = 16; i < 20; i += 2) {
                    ulonglong2 q0 = *(const ulonglong2*)(ua + 8 * (i - 16));
                    ulonglong2 q1 = *(const ulonglong2*)(ua + 8 * (i - 16) + 8);
                    FFMA2(b0, wreg[2*i],   q0.x); FFMA2(b1, wreg[2*i+1], q0.y);
                    FFMA2(b0, wreg[2*i+2], q1.x); FFMA2(b1, wreg[2*i+3], q1.y);
                }
                #pragma unroll
                for (int i = 20; i < 24; i += 2) {
                    ulonglong2 q0 = *(const ulonglong2*)(ub + 8 * (i - 20));
                    ulonglong2 q1 = *(const ulonglong2*)(ub + 8 * (i - 20) + 8);
                    FFMA2(b0, wreg[2*i],   q0.x); FFMA2(b1, wreg[2*i+1], q0.y);
                    FFMA2(b0, wreg[2*i+2], q1.x); FFMA2(b1, wreg[2*i+3], q1.y);
                }
                ADDF2(pu, b0, b1);
            }
            BARB(barid);
        }
        // epilogue flush: steps 2032..2047
        flush16(ring, gv4, TT - 16, bt);
    } else {
        // ================= X half: 16 crit chunks + 4 pu chunks ===========
        unsigned long long wreg[40];
        {
            const unsigned long long* grow = (const unsigned long long*)(gWT + (128 + idx) * 96);
            #pragma unroll
            for (int i = 0; i < 40; i++) wreg[i] = grow[i];
        }
        const bool stager = (widx == 0);
        float u_next = 0.0f;
        if (h == 0) ring[row] = 0.0f;      // x_0 (slot 0)
        if (stager) {
            vu[lane]      = uptr[lane];             // u_0
            vu[32 + lane] = uptr[NU + lane];        // u_1
            vu[64 + lane] = uptr[2 * NU + lane];    // u_2
            u_next = uptr[3 * NU + lane];           // u_3
        }
        BARB(barid);

        // pu for step 0: B1til u_0
        unsigned long long pu;
        {
            const float* ua = vu + 4 * h;
            unsigned long long b0 = 0ull, b1 = 0ull;
            #pragma unroll
            for (int i = 16; i < 20; i += 2) {
                ulonglong2 q0 = *(const ulonglong2*)(ua + 8 * (i - 16));
                ulonglong2 q1 = *(const ulonglong2*)(ua + 8 * (i - 16) + 8);
                FFMA2(b0, wreg[2*i],   q0.x); FFMA2(b1, wreg[2*i+1], q0.y);
                FFMA2(b0, wreg[2*i+2], q1.x); FFMA2(b1, wreg[2*i+3], q1.y);
            }
            ADDF2(pu, b0, b1);
        }
        BARB(barid);

        for (int t = 0; t < TT; t++) {
            if ((t & 15) == 0 && t != 0) flush16(ring, gv4, t - 16, bt);

            const float* vp = ring + (t & 31) * 128 + 4 * h;
            unsigned long long a0=0ull,a1=0ull,a2=0ull,a3=0ull;
            #pragma unroll
            for (int i = 0; i < 8; i += 2) {
                ulonglong2 v0 = *(const ulonglong2*)(vp + 8 * i);
                ulonglong2 v1 = *(const ulonglong2*)(vp + 8 * i + 8);
                FFMA2(a0, wreg[2*i],   v0.x); FFMA2(a1, wreg[2*i+1], v0.y);
                FFMA2(a2, wreg[2*i+2], v1.x); FFMA2(a3, wreg[2*i+3], v1.y);
            }
            #pragma unroll
            for (int i = 8; i < 16; i += 2) {
                ulonglong2 v0 = *(const ulonglong2*)(vp + 64 + 8 * (i - 8));
                ulonglong2 v1 = *(const ulonglong2*)(vp + 64 + 8 * (i - 8) + 8);
                FFMA2(a0, wreg[2*i],   v0.x); FFMA2(a1, wreg[2*i+1], v0.y);
                FFMA2(a2, wreg[2*i+2], v1.x); FFMA2(a3, wreg[2*i+3], v1.y);
            }
            ADDF2(a0, a0, a2); ADDF2(a1, a1, a3);
            ADDF2(a0, a0, a1); ADDF2(a0, a0, pu);
            float2 pp = u64_as_f2(a0);
            float acc = pp.x + pp.y;
            acc += __shfl_xor_sync(0xffffffffu, acc, 1);
            if (h == 0) ring[((t + 1) & 31) * 128 + row] = acc;   // x_{t+1}

            if (stager) {
                vu[((t + 3) & 3) * 32 + lane] = u_next;   // u_{t+3}
                if (t + 4 < TT) u_next = uptr[(size_t)(t + 4) * NU + lane];
            }
            // pu for next step: B1til u_{t+1}
            {
                const float* ua = vu + ((t + 1) & 3) * 32 + 4 * h;
                unsigned long long b0 = 0ull, b1 = 0ull;
                #pragma unroll
                for (int i = 16; i < 20; i += 2) {
                    ulonglong2 q0 = *(const ulonglong2*)(ua + 8 * (i - 16));
                    ulonglong2 q1 = *(const ulonglong2*)(ua + 8 * (i - 16) + 8);
                    FFMA2(b0, wreg[2*i],   q0.x); FFMA2(b1, wreg[2*i+1], q0.y);
                    FFMA2(b0, wreg[2*i+2], q1.x); FFMA2(b1, wreg[2*i+3], q1.y);
                }
                ADDF2(pu, b0, b1);
            }
            BARB(barid);
        }
        flush16(ring, gv4, TT - 16, bt);

        if (write_xfinal && h == 0) {
            // x_TT lives at ring slot (TT & 31) = 0
            out[(size_t)BB * TT * NY + (size_t)bg * NX + row] = ring[row];
        }
    }
}

// ---------------------------------------------------------------------------
// y-pass: weight-persistent, 32-timestep rounds. Grid (BB, 4), 256 threads,
// occ 2. Thread = (g in 0..3, j, h): 8 timesteps per round; y half-row
// (40 u64) in registers; v = [x|w|u] staged per round in smem.
// ---------------------------------------------------------------------------
__global__ void __launch_bounds__(256, 2)
ypass_kernel(const float* __restrict__ xpred, float* __restrict__ out)
{
    __shared__ __align__(16) float sv2[32 * 160];

    const int b   = blockIdx.x;
    const int seg = blockIdx.y;       // 0..3 -> t range [seg*512, seg*512+512)
    const int tid = threadIdx.x;
    const int g = tid >> 6;           // 0..3
    const int q = tid & 63;
    const int j = q >> 1, h = q & 1;

    const float4* gv4 = (const float4*)(gVseq + (size_t)b * TT * 128);
    const float4* u4  = (const float4*)(xpred + (size_t)b * TT * NU);
    float* yout = out + (size_t)b * TT * NY;

    unsigned long long wreg[40];
    {
        const unsigned long long* grow = (const unsigned long long*)(gWT + (256 + q) * 96);
        #pragma unroll
        for (int i = 0; i < 40; i++) wreg[i] = grow[i];
    }

    for (int rnd = 0; rnd < 16; rnd++) {
        const int t0 = seg * 512 + rnd * 32;
        // stage 32 timesteps: [x|w] (32 f4) + u (8 f4) per step
        for (int e = tid; e < 1280; e += 256) {
            int tl = e / 40, k = e - tl * 40;
            float4 val = (k < 32) ? gv4[(size_t)(t0 + tl) * 32 + k]
                                  : u4[(size_t)(t0 + tl) * 8 + (k - 32)];
            *(float4*)(sv2 + tl * 160 + 4 * k) = val;
        }
        __syncthreads();

        #pragma unroll
        for (int m = 0; m < 8; m++) {
            const int tl = g + 4 * m;
            const float* vh = sv2 + tl * 160 + 4 * h;
            unsigned long long a0=0ull,a1=0ull,a2=0ull,a3=0ull;
            #pragma unroll
            for (int i = 0; i < 16; i += 2) {
                ulonglong2 v0 = *(const ulonglong2*)(vh + 8 * i);
                ulonglong2 v1 = *(const ulonglong2*)(vh + 8 * i + 8);
                FFMA2(a0, wreg[2*i],   v0.x); FFMA2(a1, wreg[2*i+1], v0.y);
                FFMA2(a2, wreg[2*i+2], v1.x); FFMA2(a3, wreg[2*i+3], v1.y);
            }
            #pragma unroll
            for (int i = 16; i < 20; i += 2) {
                ulonglong2 v0 = *(const ulonglong2*)(vh + 128 + 8 * (i - 16));
                ulonglong2 v1 = *(const ulonglong2*)(vh + 128 + 8 * (i - 16) + 8);
                FFMA2(a0, wreg[2*i],   v0.x); FFMA2(a1, wreg[2*i+1], v0.y);
                FFMA2(a2, wreg[2*i+2], v1.x); FFMA2(a3, wreg[2*i+3], v1.y);
            }
            ADDF2(a0, a0, a2); ADDF2(a1, a1, a3); ADDF2(a0, a0, a1);
            float2 pp = u64_as_f2(a0);
            float acc = pp.x + pp.y;
            acc += __shfl_xor_sync(0xffffffffu, acc, 1);
            if (h == 0) yout[(size_t)(t0 + tl) * NY + j] = acc;
        }
        __syncthreads();
    }
}

// ---------------------------------------------------------------------------
extern "C" void kernel_launch(void* const* d_in, const int* in_sizes, int n_in,
                              void* d_out, int out_size)
{
    const float* xpred   = (const float*)d_in[0];
    const float* Y       = (const float*)d_in[1];
    const float* lambdas = (const float*)d_in[2];
    const float* A       = (const float*)d_in[3];
    const float* B1      = (const float*)d_in[4];
    const float* B2      = (const float*)d_in[5];
    const float* C1      = (const float*)d_in[6];
    const float* D11     = (const float*)d_in[7];
    const float* D12     = (const float*)d_in[8];
    const float* C2      = (const float*)d_in[9];
    const float* D21     = (const float*)d_in[10];

    (void)in_sizes; (void)n_in;

    inv_kernel<<<1, 256>>>(Y);
    fold_kernel<<<160, 128>>>(lambdas, A, B1, B2, C1, D11, D12, C2, D21);

    int write_xfinal = (out_size >= BB * TT * NY + BB * NX) ? 1 : 0;
    rnn_kernel<<<BB / 2, 512>>>(xpred, (float*)d_out, write_xfinal);

    dim3 ygrid(BB, 4);
    ypass_kernel<<<ygrid, 256>>>(xpred, (float*)d_out);
}

// round 14
// speedup vs baseline: 1.5256x; 1.5256x over previous
#include <cuda_runtime.h>
#include <cstddef>

// Problem constants
#define NX 64
#define NU 32
#define NY 32
#define NW 64
#define BB 256
#define TT 2048

// Yinv^T (written by inv_kernel): gYinvT[j*64+i] = Yinv[i][j]
__device__ float gYinvT[64 * 64];

// Per-thread packed weights gWT[s][96] (R10 layout; chunk = 4 floats = 2 u64):
//  s in [0,64)   : z row s = [C2t(64)|D21t(32)] contiguous, chunks 0..23
//  s in [64,192) : x half: idx=s-64, row 64+(idx>>1)=[Atil(64)|B1til(32)|B2til(64)],
//                  h=idx&1. i0..7: c=h+2i; i8..11: c=16+h+2(i-8); i12..19: c=24+h+2(i-12)
//  s in [192,256): y half: idx=s-192, row=[C1(64)|D11(32)|D12(64)], same map
__device__ float gWT[256 * 96];

// ---------------------------------------------------------------------------
// inv_kernel: Newton-Schulz inverse of Y (X0 = 2I - Y, 3 iters), all in smem.
// ---------------------------------------------------------------------------
__global__ void __launch_bounds__(256, 1)
inv_kernel(const float* __restrict__ Y)
{
    __shared__ float sY[4096];
    __shared__ float sX[4096];
    __shared__ float sQ[4096];
    const int tid = threadIdx.x;      // 256
    const int row = tid >> 2;         // 0..63
    const int g16 = tid & 3;          // 16-col group

    for (int e = tid; e < 4096; e += 256) sY[e] = Y[e];
    __syncthreads();
    for (int e = tid; e < 4096; e += 256) {
        int i = e >> 6, j = e & 63;
        sX[e] = ((i == j) ? 2.0f : 0.0f) - sY[e];
    }
    __syncthreads();

    for (int it = 0; it < 3; it++) {
        float acc[16];
        #pragma unroll
        for (int m = 0; m < 16; m++) acc[m] = 0.0f;
        for (int k = 0; k < 64; k++) {
            float a = sY[row * 64 + k];
            const float4* xr = (const float4*)(sX + k * 64 + g16 * 16);
            float4 x0 = xr[0], x1 = xr[1], x2 = xr[2], x3 = xr[3];
            acc[0]+=a*x0.x; acc[1]+=a*x0.y; acc[2]+=a*x0.z; acc[3]+=a*x0.w;
            acc[4]+=a*x1.x; acc[5]+=a*x1.y; acc[6]+=a*x1.z; acc[7]+=a*x1.w;
            acc[8]+=a*x2.x; acc[9]+=a*x2.y; acc[10]+=a*x2.z; acc[11]+=a*x2.w;
            acc[12]+=a*x3.x; acc[13]+=a*x3.y; acc[14]+=a*x3.z; acc[15]+=a*x3.w;
        }
        #pragma unroll
        for (int m = 0; m < 16; m++) {
            int j = g16 * 16 + m;
            sQ[row * 64 + j] = ((j == row) ? 2.0f : 0.0f) - acc[m];
        }
        __syncthreads();
        #pragma unroll
        for (int m = 0; m < 16; m++) acc[m] = 0.0f;
        for (int k = 0; k < 64; k++) {
            float a = sX[row * 64 + k];
            const float4* qr = (const float4*)(sQ + k * 64 + g16 * 16);
            float4 q0 = qr[0], q1 = qr[1], q2 = qr[2], q3 = qr[3];
            acc[0]+=a*q0.x; acc[1]+=a*q0.y; acc[2]+=a*q0.z; acc[3]+=a*q0.w;
            acc[4]+=a*q1.x; acc[5]+=a*q1.y; acc[6]+=a*q1.z; acc[7]+=a*q1.w;
            acc[8]+=a*q2.x; acc[9]+=a*q2.y; acc[10]+=a*q2.z; acc[11]+=a*q2.w;
            acc[12]+=a*q3.x; acc[13]+=a*q3.y; acc[14]+=a*q3.z; acc[15]+=a*q3.w;
        }
        __syncthreads();
        #pragma unroll
        for (int m = 0; m < 16; m++) sX[row * 64 + g16 * 16 + m] = acc[m];
        __syncthreads();
    }
    for (int e = tid; e < 4096; e += 256) {
        int i = e >> 6, j = e & 63;
        gYinvT[j * 64 + i] = sX[e];
    }
}

// ---------------------------------------------------------------------------
// fold_kernel: grid 160 — CTA r builds fused row r, writes gWT (R10 layout).
// Row layout: [ *x-part(64) | *u-part(32) | *w-part(64) ]:
//   z (r<64):       [ C2/lam | D21/lam | 0 ]
//   x (64<=r<128):  [ Atil   | B1til   | B2til ]
//   y (r>=128):     [ C1     | D11     | D12 ]
// ---------------------------------------------------------------------------
__global__ void __launch_bounds__(128, 1)
fold_kernel(const float* __restrict__ lambdas,
            const float* __restrict__ A,
            const float* __restrict__ B1,
            const float* __restrict__ B2,
            const float* __restrict__ C1,
            const float* __restrict__ D11,
            const float* __restrict__ D12,
            const float* __restrict__ C2,
            const float* __restrict__ D21)
{
    __shared__ float svv[64];
    __shared__ float rowbuf[160];
    const int r = blockIdx.x;    // 0..159
    const int t = threadIdx.x;   // 0..127

    if (r < 64) {
        // z row: straight copy with 1/lambda scaling; pack = contiguous 96
        float linv = 1.0f / lambdas[r];
        if (t < 64)       rowbuf[t] = C2[r * 64 + t] * linv;
        else if (t < 96)  rowbuf[t] = D21[r * 32 + (t - 64)] * linv;
        __syncthreads();
        if (t < 96) gWT[r * 96 + t] = rowbuf[t];
    } else if (r < 128) {
        // x row: YinvT-row @ [A, B1, B2]
        int j = r - 64;
        if (t < 64) svv[t] = gYinvT[j * 64 + t];
        __syncthreads();
        if (t < 64) {
            float aa = 0.0f, ab = 0.0f;
            #pragma unroll 8
            for (int i = 0; i < 64; i++) {
                float yi = svv[i];
                aa += yi * A[i * 64 + t];
                ab += yi * B2[i * 64 + t];
            }
            rowbuf[t]      = aa;
            rowbuf[96 + t] = ab;
        } else if (t < 96) {
            int m = t - 64;
            float au = 0.0f;
            #pragma unroll 8
            for (int i = 0; i < 64; i++) au += svv[i] * B1[i * 32 + m];
            rowbuf[64 + m] = au;
        }
        __syncthreads();
        // pack 2 half-slots (20 chunks each)
        for (int e = t; e < 160; e += 128) {
            int h = (e >= 80) ? 1 : 0;
            int ee = e - 80 * h;
            int i = ee >> 2, jj = ee & 3;
            int c;
            if (i < 8)       c = h + 2 * i;
            else if (i < 12) c = 16 + h + 2 * (i - 8);
            else             c = 24 + h + 2 * (i - 12);
            gWT[(64 + 2 * j + h) * 96 + ee] = rowbuf[4 * c + jj];
        }
    } else {
        // y row: [C1 | D11 | D12]
        int j = r - 128;
        if (t < 64) {
            rowbuf[t]      = C1[j * 64 + t];
            rowbuf[96 + t] = D12[j * 64 + t];
        } else if (t < 96) {
            rowbuf[64 + (t - 64)] = D11[j * 32 + (t - 64)];
        }
        __syncthreads();
        for (int e = t; e < 160; e += 128) {
            int h = (e >= 80) ? 1 : 0;
            int ee = e - 80 * h;
            int i = ee >> 2, jj = ee & 3;
            int c;
            if (i < 8)       c = h + 2 * i;
            else if (i < 12) c = 16 + h + 2 * (i - 8);
            else             c = 24 + h + 2 * (i - 12);
            gWT[(192 + 2 * j + h) * 96 + ee] = rowbuf[4 * c + jj];
        }
    }
}

// ---------------------------------------------------------------------------
// helpers
// ---------------------------------------------------------------------------
__device__ __forceinline__ float2 u64_as_f2(unsigned long long x) {
    float2 r;
    asm("mov.b64 {%0, %1}, %2;" : "=f"(r.x), "=f"(r.y) : "l"(x));
    return r;
}
#define FFMA2(acc, w, vv) \
    asm("fma.rn.f32x2 %0, %1, %2, %0;" : "+l"(acc) : "l"(w), "l"(vv))
#define ADDF2(d, a, b) \
    asm("add.rn.f32x2 %0, %1, %2;" : "=l"(d) : "l"(a), "l"(b))

__device__ __forceinline__ float fast_tanh(float x) {
    float e;
    asm("ex2.approx.f32 %0, %1;" : "=f"(e) : "f"(x * 2.8853900817779268f));
    return 1.0f - __fdividef(2.0f, e + 1.0f);
}

// ---------------------------------------------------------------------------
// Main recurrent kernel: 256 CTAs x 256 threads, ONE batch chain per CTA,
// 2 CTAs co-resident per SM (launch_bounds(256,2)) — independent chains fill
// each other's barrier-stall windows. Structure = R10's proven loop:
//   Phase A: all dot x-part (z: 16 chunks full row; x/y: 8 half-chunks),
//            z publishes w via tanh; y-warp-6 stages u.
//   Phase B: x/y add w-part + u0, publish x_{t+1} / stream y_t;
//            z computes its u-partial for t+1; x/y recompute theirs.
// Warp roles: x = wid 0..3 (1/SMSP), z = wid 4..5, y = wid 6..7 (6 = stager).
// smem: vx[64] | vw[64] | vu[2][32].
// ---------------------------------------------------------------------------
__global__ void __launch_bounds__(256, 2)
rnn_kernel(const float* __restrict__ xpred, float* __restrict__ out, int write_xfinal)
{
    __shared__ __align__(16) float sv[192];

    const int tid  = threadIdx.x;
    const int wid  = tid >> 5;
    const int lane = tid & 31;

    const int isZ = (wid == 4 || wid == 5);
    const int isY = (wid >= 6);

    float* vx = sv;          // x_t [64]
    float* vw = sv + 64;     // w_t [64]
    float* vu = sv + 128;    // u   [2][32]
    const int bg = blockIdx.x;
    const float* uptr = xpred + (size_t)bg * TT * NU;
    float* yout = out + (size_t)bg * TT * NY;

    if (isZ) {
        // ================= Z path: full row (96 w), crit 16 chunks ========
        const int zr = (wid - 4) * 32 + lane;     // z row 0..63
        unsigned long long wreg[48];
        {
            const unsigned long long* grow = (const unsigned long long*)(gWT + zr * 96);
            #pragma unroll
            for (int i = 0; i < 48; i++) wreg[i] = grow[i];
        }

        vx[zr] = 0.0f;                 // x0 = 0
        __syncthreads();               // u_0 staged by y warp

        // prologue: u-partial for t=0 (weights u64 32..47 over vu buf0)
        unsigned long long u0, u1z = 0ull, u0z = 0ull;
        {
            const float* ub = vu;
            #pragma unroll
            for (int c = 0; c < 8; c += 2) {
                ulonglong2 q0 = *(const ulonglong2*)(ub + 4 * c);
                ulonglong2 q1 = *(const ulonglong2*)(ub + 4 * c + 4);
                FFMA2(u0z, wreg[32 + 2*c],     q0.x);
                FFMA2(u1z, wreg[32 + 2*c + 1], q0.y);
                FFMA2(u0z, wreg[32 + 2*c + 2], q1.x);
                FFMA2(u1z, wreg[32 + 2*c + 3], q1.y);
            }
            ADDF2(u0, u0z, u1z);
        }

        for (int t = 0; t < TT; t++) {
            // ---- Phase A: x-part (16 chunks) + combine + tanh ----
            unsigned long long a0=0ull,a1=0ull,a2=0ull,a3=0ull;
            #pragma unroll
            for (int c = 0; c < 16; c += 2) {
                ulonglong2 v0 = *(const ulonglong2*)(vx + 4 * c);
                ulonglong2 v1 = *(const ulonglong2*)(vx + 4 * c + 4);
                FFMA2(a0, wreg[2*c],   v0.x);
                FFMA2(a1, wreg[2*c+1], v0.y);
                FFMA2(a2, wreg[2*c+2], v1.x);
                FFMA2(a3, wreg[2*c+3], v1.y);
            }
            ADDF2(a0, a0, a2); ADDF2(a1, a1, a3);
            ADDF2(a0, a0, a1); ADDF2(a0, a0, u0);
            float2 p = u64_as_f2(a0);
            vw[zr] = fast_tanh(p.x + p.y);   // publish w_t
            __syncthreads();                  // barA

            // ---- Phase B: u-partial for t+1 (buf (t+1)&1) ----
            {
                const float* ub = vu + ((t + 1) & 1) * 32;
                unsigned long long b0=0ull,b1=0ull,b2=0ull,b3=0ull;
                #pragma unroll
                for (int c = 0; c < 8; c += 2) {
                    ulonglong2 q0 = *(const ulonglong2*)(ub + 4 * c);
                    ulonglong2 q1 = *(const ulonglong2*)(ub + 4 * c + 4);
                    FFMA2(b0, wreg[32 + 2*c],     q0.x);
                    FFMA2(b1, wreg[32 + 2*c + 1], q0.y);
                    FFMA2(b2, wreg[32 + 2*c + 2], q1.x);
                    FFMA2(b3, wreg[32 + 2*c + 3], q1.y);
                }
                ADDF2(b0, b0, b2); ADDF2(b1, b1, b3); ADDF2(u0, b0, b1);
            }
            __syncthreads();                  // barB: x_{t+1}, u staged
        }

        if (write_xfinal) {
            out[(size_t)BB * TT * NY + (size_t)bg * NX + zr] = vx[zr];
        }
    } else {
        // ================= X / Y path: half row, 8+8 crit chunks ==========
        const int idx = isY ? ((wid - 6) * 32 + lane) : (wid * 32 + lane);
        const int h   = idx & 1;
        const int j   = idx >> 1;             // x: state row; y: output col
        const bool stager = (wid == 6);       // u staging lanes
        unsigned long long wreg[40];
        {
            const int s = (isY ? 192 : 64) + idx;
            const unsigned long long* grow = (const unsigned long long*)(gWT + s * 96);
            #pragma unroll
            for (int i = 0; i < 40; i++) wreg[i] = grow[i];
        }

        // stage u_0 into buf0; u_next = u_1
        float u_next = 0.0f;
        if (stager) {
            vu[lane] = uptr[lane];
            u_next = uptr[NU + lane];
        }
        __syncthreads();

        const float* vxh = vx + 4 * h;
        const float* vwh = vw + 4 * h;

        // prologue: u-partial for t=0 (4 chunks, weights u64 16..23)
        unsigned long long u0;
        {
            const float* ub = vu + 4 * h;
            unsigned long long b0 = 0ull, b1 = 0ull;
            #pragma unroll
            for (int i = 8; i < 12; i += 2) {
                ulonglong2 q0 = *(const ulonglong2*)(ub + 8 * (i - 8));
                ulonglong2 q1 = *(const ulonglong2*)(ub + 8 * (i - 8) + 8);
                FFMA2(b0, wreg[2*i],   q0.x);
                FFMA2(b1, wreg[2*i+1], q0.y);
                FFMA2(b0, wreg[2*i+2], q1.x);
                FFMA2(b1, wreg[2*i+3], q1.y);
            }
            ADDF2(u0, b0, b1);
        }

        for (int t = 0; t < TT; t++) {
            // ---- Phase A: x-part (8 chunks, i=0..7); stager refreshes u ----
            unsigned long long a0=0ull,a1=0ull,a2=0ull,a3=0ull;
            #pragma unroll
            for (int i = 0; i < 8; i += 2) {
                ulonglong2 v0 = *(const ulonglong2*)(vxh + 8 * i);
                ulonglong2 v1 = *(const ulonglong2*)(vxh + 8 * i + 8);
                FFMA2(a0, wreg[2*i],   v0.x);
                FFMA2(a1, wreg[2*i+1], v0.y);
                FFMA2(a2, wreg[2*i+2], v1.x);
                FFMA2(a3, wreg[2*i+3], v1.y);
            }
            if (stager) {
                vu[((t + 1) & 1) * 32 + lane] = u_next;   // u_{t+1}
                if (t + 2 < TT) u_next = uptr[(size_t)(t + 2) * NU + lane];
            }
            __syncthreads();   // barA: w_t visible

            // ---- Phase B: w-part (8 chunks, i=12..19) + publish ----
            #pragma unroll
            for (int i = 12; i < 20; i += 2) {
                ulonglong2 v0 = *(const ulonglong2*)(vwh + 8 * (i - 12));
                ulonglong2 v1 = *(const ulonglong2*)(vwh + 8 * (i - 12) + 8);
                FFMA2(a0, wreg[2*i],   v0.x);
                FFMA2(a1, wreg[2*i+1], v0.y);
                FFMA2(a2, wreg[2*i+2], v1.x);
                FFMA2(a3, wreg[2*i+3], v1.y);
            }
            ADDF2(a0, a0, a2); ADDF2(a1, a1, a3);
            ADDF2(a0, a0, a1); ADDF2(a0, a0, u0);
            float2 p = u64_as_f2(a0);
            float acc = p.x + p.y;
            acc += __shfl_xor_sync(0xffffffffu, acc, 1);   // combine halves
            if (h == 0) {
                if (!isY) vx[j] = acc;                       // publish x_{t+1}
                else      yout[(size_t)t * NY + j] = acc;    // stream y_t
            }

            // u-partial for t+1 (4 chunks, buf (t+1)&1) — off critical path
            {
                const float* ub = vu + ((t + 1) & 1) * 32 + 4 * h;
                unsigned long long b0 = 0ull, b1 = 0ull;
                #pragma unroll
                for (int i = 8; i < 12; i += 2) {
                    ulonglong2 q0 = *(const ulonglong2*)(ub + 8 * (i - 8));
                    ulonglong2 q1 = *(const ulonglong2*)(ub + 8 * (i - 8) + 8);
                    FFMA2(b0, wreg[2*i],   q0.x);
                    FFMA2(b1, wreg[2*i+1], q0.y);
                    FFMA2(b0, wreg[2*i+2], q1.x);
                    FFMA2(b1, wreg[2*i+3], q1.y);
                }
                ADDF2(u0, b0, b1);
            }
            __syncthreads();   // barB: x_{t+1}, u staged
        }
    }
}

// ---------------------------------------------------------------------------
extern "C" void kernel_launch(void* const* d_in, const int* in_sizes, int n_in,
                              void* d_out, int out_size)
{
    const float* xpred   = (const float*)d_in[0];
    const float* Y       = (const float*)d_in[1];
    const float* lambdas = (const float*)d_in[2];
    const float* A       = (const float*)d_in[3];
    const float* B1      = (const float*)d_in[4];
    const float* B2      = (const float*)d_in[5];
    const float* C1      = (const float*)d_in[6];
    const float* D11     = (const float*)d_in[7];
    const float* D12     = (const float*)d_in[8];
    const float* C2      = (const float*)d_in[9];
    const float* D21     = (const float*)d_in[10];

    (void)in_sizes; (void)n_in;

    inv_kernel<<<1, 256>>>(Y);
    fold_kernel<<<160, 128>>>(lambdas, A, B1, B2, C1, D11, D12, C2, D21);

    int write_xfinal = (out_size >= BB * TT * NY + BB * NX) ? 1 : 0;
    rnn_kernel<<<BB, 256>>>(xpred, (float*)d_out, write_xfinal);
}